// round 7
// baseline (speedup 1.0000x reference)
#include <cuda_runtime.h>

#define BATCH 64
#define SEQ   512
#define EMB   512
#define HID   1024
#define G4    4096
#define CHUNK 64
#define NCHUNK (SEQ / CHUNK)
#define NBLK  128
#define LNEPS 1e-5f

typedef unsigned long long ull;

// ---------------- scratch (device globals; no allocs allowed) ----------------
__device__ float g_xg[(size_t)CHUNK * BATCH * G4];   // 64MB: chunk of xg incl. b_i
__device__ float g_part[(size_t)8 * BATCH * G4];     // 8MB: K-slice partials [ks][b][col]
__device__ ull   g_h[32 * HID];                      // h packed f32x2: [bp][k] -> (b=2bp, b=2bp+1)
__device__ float g_c[BATCH * HID];                   // LN'd cell state [b][j]
__device__ unsigned g_cnt, g_gen;                    // grid barrier (monotonic, replay-safe)

// ---------------- helpers ----------------
static __device__ __forceinline__ ull pk2(float lo, float hi) {
    ull r; asm("mov.b64 %0, {%1,%2};" : "=l"(r) : "f"(lo), "f"(hi)); return r;
}
static __device__ __forceinline__ void upk2(ull v, float& lo, float& hi) {
    asm("mov.b64 {%0,%1}, %2;" : "=f"(lo), "=f"(hi) : "l"(v));
}
static __device__ __forceinline__ ull ffma2(ull a, ull b, ull c) {
    ull d; asm("fma.rn.f32x2 %0, %1, %2, %3;" : "=l"(d) : "l"(a), "l"(b), "l"(c)); return d;
}
static __device__ __forceinline__ unsigned ldacq(unsigned* p) {
    unsigned v; asm volatile("ld.acquire.gpu.u32 %0, [%1];" : "=r"(v) : "l"(p) : "memory"); return v;
}

// grid barrier: monotonic epochs, safe across graph replays.
static __device__ __forceinline__ void gridbar(unsigned gen0, int& bl) {
    __syncthreads();
    if (threadIdx.x == 0) {
        bl++;
        __threadfence();
        unsigned a = atomicAdd(&g_cnt, 1u);
        if ((a + 1u) % NBLK == 0u) {
            __threadfence();
            atomicAdd(&g_gen, 1u);
        } else {
            while ((int)(ldacq(&g_gen) - gen0) < bl) __nanosleep(64);
        }
    }
    __syncthreads();
}

// 128-k MAC: acc[8bp][4cols] += h(smem f32x2) * w(global, stride 4096), depth-8 prefetch ring
static __device__ __forceinline__ void mac128(const ull* __restrict__ shb,
                                              const float* __restrict__ wp,
                                              ull (&acc)[8][4]) {
    float4 wb[8];
#pragma unroll
    for (int j = 0; j < 8; ++j) wb[j] = *(const float4*)(wp + (size_t)j * G4);
    const float* wnext = wp + (size_t)8 * G4;
#pragma unroll 1
    for (int kc = 0; kc < 16; ++kc) {
#pragma unroll
        for (int j = 0; j < 8; ++j) {
            float4 wv = wb[j];
            if (kc != 15) wb[j] = *(const float4*)(wnext + (size_t)j * G4);
            ull w0 = pk2(wv.x, wv.x), w1 = pk2(wv.y, wv.y);
            ull w2 = pk2(wv.z, wv.z), w3 = pk2(wv.w, wv.w);
            const ull* hrow = shb + (kc * 8 + j) * 32;
#pragma unroll
            for (int i = 0; i < 8; ++i) {
                ull h = hrow[i];
                acc[i][0] = ffma2(h, w0, acc[i][0]);
                acc[i][1] = ffma2(h, w1, acc[i][1]);
                acc[i][2] = ffma2(h, w2, acc[i][2]);
                acc[i][3] = ffma2(h, w3, acc[i][3]);
            }
        }
        wnext += (size_t)8 * G4;
    }
}

__global__ __launch_bounds__(256, 1) void encPersist(
    const int* __restrict__ src, const float* __restrict__ emb,
    const float* __restrict__ Wi, const float* __restrict__ bi,
    const float* __restrict__ Wh, const float* __restrict__ bh,
    const float* __restrict__ gamma, const float* __restrict__ beta,
    float* __restrict__ out)
{
    __shared__ ull sh[128 * 32];          // 32KB: h / A staging [k][pair]
    __shared__ float rbuf[8], vbuf[8];
    __shared__ float s_mu, s_rstd;

    const int tid = threadIdx.x;
    const int blk = blockIdx.x;
    const int w = tid >> 5, lane = tid & 31;
    const int bps = lane >> 3, cs = lane & 7;

    unsigned gen0 = 0;
    if (tid == 0) gen0 = ldacq(&g_gen);
    int bl = 0;

    // zero state each launch (replay-safe)
    for (int i = blk * 256 + tid; i < BATCH * HID; i += NBLK * 256) g_c[i] = 0.f;
    for (int i = blk * 256 + tid; i < 32 * HID; i += NBLK * 256) g_h[i] = 0ull;
    gridbar(gen0, bl);

    const size_t HSEQ = (size_t)BATCH * SEQ * HID;

    for (int chunk = 0; chunk < NCHUNK; ++chunk) {
        // ======== phase A: xg for this chunk ========
        for (int ti = blk; ti < 1024; ti += NBLK) {
            const int mt = ti >> 4;          // timestep-in-chunk (64 rows = all b)
            const int nt = ti & 15;          // 256-col tile
            const int t = chunk * CHUNK + mt;
            const int colbase = nt * 256 + w * 32 + cs * 4;
            ull acc[8][4];
#pragma unroll
            for (int i = 0; i < 8; ++i)
#pragma unroll
                for (int c = 0; c < 4; ++c) acc[i][c] = 0ull;

            for (int kc2 = 0; kc2 < 4; ++kc2) {
                const int k0 = kc2 * 128;
                // stage A: 64 rows (b) x 128 k, packed pairs sh[k][bp]
                {
                    int r = tid >> 2, seg = tid & 3;
                    int s = __ldg(src + r * SEQ + t);
                    float* shf = (float*)sh;
#pragma unroll
                    for (int q = 0; q < 8; ++q) {
                        int kk = seg * 32 + q * 4;
                        float4 v = make_float4(0.f, 0.f, 0.f, 0.f);
                        if (s != 0) v = *(const float4*)(emb + (size_t)s * EMB + k0 + kk);
                        shf[(kk + 0) * 64 + r] = v.x;
                        shf[(kk + 1) * 64 + r] = v.y;
                        shf[(kk + 2) * 64 + r] = v.z;
                        shf[(kk + 3) * 64 + r] = v.w;
                    }
                }
                __syncthreads();
                mac128(sh + bps * 8, Wi + (size_t)k0 * G4 + colbase, acc);
                __syncthreads();
            }
            float4 bv = *(const float4*)(bi + colbase);
#pragma unroll
            for (int i = 0; i < 8; ++i) {
                int b0 = (bps * 8 + i) * 2;
                float4 lo4, hi4;
                upk2(acc[i][0], lo4.x, hi4.x); upk2(acc[i][1], lo4.y, hi4.y);
                upk2(acc[i][2], lo4.z, hi4.z); upk2(acc[i][3], lo4.w, hi4.w);
                lo4.x += bv.x; lo4.y += bv.y; lo4.z += bv.z; lo4.w += bv.w;
                hi4.x += bv.x; hi4.y += bv.y; hi4.z += bv.z; hi4.w += bv.w;
                *(float4*)(g_xg + (size_t)(mt * 64 + b0) * G4 + colbase) = lo4;
                *(float4*)(g_xg + (size_t)(mt * 64 + b0 + 1) * G4 + colbase) = hi4;
            }
        }
        gridbar(gen0, bl);

        // ======== recurrence over this chunk ========
        for (int tl = 0; tl < CHUNK; ++tl) {
            const int t = chunk * CHUNK + tl;

            // ---- G: partial gate GEMM, 16 col-blocks x 8 k-slices ----
            {
                const int cb = blk & 15, ks = blk >> 4;
                const int colbase = cb * 256 + w * 32 + cs * 4;
                const int kbase = ks * 128;
                for (int i = tid; i < 4096; i += 256) {
                    int bp = i >> 7, kk = i & 127;
                    sh[kk * 32 + bp] = __ldcg(g_h + bp * HID + kbase + kk);
                }
                __syncthreads();
                ull acc[8][4];
#pragma unroll
                for (int i = 0; i < 8; ++i)
#pragma unroll
                    for (int c = 0; c < 4; ++c) acc[i][c] = 0ull;
                mac128(sh + bps * 8, Wh + (size_t)kbase * G4 + colbase, acc);
#pragma unroll
                for (int i = 0; i < 8; ++i) {
                    int b0 = (bps * 8 + i) * 2;
                    float4 lo4, hi4;
                    upk2(acc[i][0], lo4.x, hi4.x); upk2(acc[i][1], lo4.y, hi4.y);
                    upk2(acc[i][2], lo4.z, hi4.z); upk2(acc[i][3], lo4.w, hi4.w);
                    *(float4*)(g_part + (size_t)(ks * 64 + b0) * G4 + colbase) = lo4;
                    *(float4*)(g_part + (size_t)(ks * 64 + b0 + 1) * G4 + colbase) = hi4;
                }
            }
            gridbar(gen0, bl);

            // ---- R: reduce + gates + c + LN + h (blocks 0..63, one b each) ----
            if (blk < BATCH) {
                const int b = blk;
                float c4[4], o4[4];
                float sum = 0.f;
#pragma unroll
                for (int r = 0; r < 4; ++r) {
                    int j = tid + r * 256;
                    float pg[4];
#pragma unroll
                    for (int gi = 0; gi < 4; ++gi) {
                        int col = gi * HID + j;
                        float s = __ldg(bh + col) +
                                  __ldcg(g_xg + (size_t)(tl * 64 + b) * G4 + col);
#pragma unroll
                        for (int ksi = 0; ksi < 8; ++ksi)
                            s += __ldcg(g_part + (size_t)(ksi * 64 + b) * G4 + col);
                        pg[gi] = s;
                    }
                    float ig = 1.f / (1.f + expf(-pg[0]));
                    float fg = 1.f / (1.f + expf(-pg[1]));
                    float og = 1.f / (1.f + expf(-pg[2]));
                    float gg = tanhf(pg[3]);
                    float cp = g_c[b * HID + j];
                    c4[r] = fg * cp + ig * gg;
                    o4[r] = og;
                    sum += c4[r];
                }
#pragma unroll
                for (int o = 16; o; o >>= 1) sum += __shfl_xor_sync(0xffffffffu, sum, o);
                if ((tid & 31) == 0) rbuf[tid >> 5] = sum;
                __syncthreads();
                if (tid < 8) {
                    float v = rbuf[tid];
#pragma unroll
                    for (int o = 4; o; o >>= 1) v += __shfl_xor_sync(0xffu, v, o);
                    if (tid == 0) s_mu = v * (1.f / 1024.f);
                }
                __syncthreads();
                const float mu = s_mu;
                float vs = 0.f;
#pragma unroll
                for (int r = 0; r < 4; ++r) { float d = c4[r] - mu; vs += d * d; }
#pragma unroll
                for (int o = 16; o; o >>= 1) vs += __shfl_xor_sync(0xffffffffu, vs, o);
                if ((tid & 31) == 0) vbuf[tid >> 5] = vs;
                __syncthreads();
                if (tid < 8) {
                    float v = vbuf[tid];
#pragma unroll
                    for (int o = 4; o; o >>= 1) v += __shfl_xor_sync(0xffu, v, o);
                    if (tid == 0) s_rstd = rsqrtf(v * (1.f / 1024.f) + LNEPS);
                }
                __syncthreads();
                const float rstd = s_rstd;
#pragma unroll
                for (int r = 0; r < 4; ++r) {
                    int j = tid + r * 256;
                    float cn = (c4[r] - mu) * rstd * __ldg(gamma + j) + __ldg(beta + j);
                    g_c[b * HID + j] = cn;
                    float hv = o4[r] * tanhf(cn);
                    ((float*)g_h)[((size_t)(b >> 1) * HID + j) * 2 + (b & 1)] = hv;
                    out[((size_t)b * SEQ + t) * HID + j] = hv;
                    if (t == SEQ - 1) {
                        out[HSEQ + (size_t)b * HID + j] = hv;
                        out[HSEQ + (size_t)BATCH * HID + (size_t)b * HID + j] = cn;
                    }
                }
            }
            gridbar(gen0, bl);
        }
    }
}

// ---------------- launch: ONE graph node ----------------
extern "C" void kernel_launch(void* const* d_in, const int* in_sizes, int n_in,
                              void* d_out, int out_size)
{
    const int*   src   = (const int*)  d_in[0];
    const float* emb   = (const float*)d_in[1];
    const float* Wi    = (const float*)d_in[2];
    const float* bi    = (const float*)d_in[3];
    const float* Wh    = (const float*)d_in[4];
    const float* bh    = (const float*)d_in[5];
    const float* gamma = (const float*)d_in[6];
    const float* beta  = (const float*)d_in[7];
    float* out = (float*)d_out;

    encPersist<<<NBLK, 256>>>(src, emb, Wi, bi, Wh, bh, gamma, beta, out);
}

// round 8
// speedup vs baseline: 1.0001x; 1.0001x over previous
#include <cuda_runtime.h>

#define BATCH 64
#define SEQ   512
#define EMB   512
#define HID   1024
#define G4    4096
#define CHUNK 64
#define NCHUNK (SEQ / CHUNK)
#define NBLK  256
#define LNEPS 1e-5f

typedef unsigned long long ull;

// ---------------- scratch (device globals; no allocs allowed) ----------------
__device__ float g_xg[(size_t)CHUNK * BATCH * G4];   // 64MB: chunk of xg incl. b_i
__device__ float g_part[(size_t)8 * BATCH * G4];     // 8MB: K-slice partials [ks][b][col]
__device__ ull   g_hT[HID * 32];                     // h f32x2, k-major: [k][pair]
__device__ float g_c[BATCH * HID];                   // LN'd cell state [b][j]
__device__ unsigned g_cnt, g_gen;                    // grid barrier (monotonic, replay-safe)

// ---------------- helpers ----------------
static __device__ __forceinline__ ull pk2(float lo, float hi) {
    ull r; asm("mov.b64 %0, {%1,%2};" : "=l"(r) : "f"(lo), "f"(hi)); return r;
}
static __device__ __forceinline__ void upk2(ull v, float& lo, float& hi) {
    asm("mov.b64 {%0,%1}, %2;" : "=f"(lo), "=f"(hi) : "l"(v));
}
static __device__ __forceinline__ ull ffma2(ull a, ull b, ull c) {
    ull d; asm("fma.rn.f32x2 %0, %1, %2, %3;" : "=l"(d) : "l"(a), "l"(b), "l"(c)); return d;
}
static __device__ __forceinline__ unsigned ldacq(unsigned* p) {
    unsigned v; asm volatile("ld.acquire.gpu.u32 %0, [%1];" : "=r"(v) : "l"(p) : "memory"); return v;
}

// grid barrier: monotonic epochs, safe across graph replays.
static __device__ __forceinline__ void gridbar(unsigned gen0, int& bl) {
    __syncthreads();
    if (threadIdx.x == 0) {
        bl++;
        __threadfence();
        unsigned a = atomicAdd(&g_cnt, 1u);
        if ((a + 1u) % NBLK == 0u) {
            __threadfence();
            atomicAdd(&g_gen, 1u);
        } else {
            while ((int)(ldacq(&g_gen) - gen0) < bl) __nanosleep(64);
        }
    }
    __syncthreads();
}

__global__ __launch_bounds__(256, 2) void encPersist(
    const int* __restrict__ src, const float* __restrict__ emb,
    const float* __restrict__ Wi, const float* __restrict__ bi,
    const float* __restrict__ Wh, const float* __restrict__ bh,
    const float* __restrict__ gamma, const float* __restrict__ beta,
    float* __restrict__ out)
{
    extern __shared__ __align__(16) char dsm[];
    float* sW  = (float*)dsm;               // 64KB: Wh slice [k 0..127][col 0..127]
    ull*   shH = (ull*)(dsm + 65536);       // 32KB: h / A staging [k][pair]

    __shared__ float rbuf[8], vbuf[8];
    __shared__ float s_mu, s_rstd;

    const int tid = threadIdx.x;
    const int blk = blockIdx.x;
    const int w = tid >> 5, lane = tid & 31;
    const int bps = lane >> 2;           // 0..7: group of 4 batch-pairs
    const int cs = lane & 3;             // 0..3
    const int cloc = w * 16 + cs * 4;    // local col 0..124

    // G decomposition: 32 col-blocks x 8 K-slices
    const int cb = blk & 31, ks = blk >> 5;
    const int kbase = ks * 128;

    unsigned gen0 = 0;
    if (tid == 0) gen0 = ldacq(&g_gen);
    int bl = 0;

    // load persistent Wh slice into smem (constant for whole run)
    {
        const float4* wsrc = (const float4*)(Wh + (size_t)kbase * G4 + cb * 128);
        // row kl: 32 float4; global row stride G4/4 float4
#pragma unroll
        for (int rr = 0; rr < 16; ++rr) {
            int i = tid + rr * 256;            // 0..4095
            int kl = i >> 5, c4 = i & 31;
            float4 v = __ldg(wsrc + (size_t)kl * (G4 / 4) + c4);
            *(float4*)&sW[kl * 128 + c4 * 4] = v;
        }
    }

    // zero state each launch (replay-safe)
    for (int i = blk * 256 + tid; i < BATCH * HID; i += NBLK * 256) g_c[i] = 0.f;
    for (int i = blk * 256 + tid; i < HID * 32; i += NBLK * 256) g_hT[i] = 0ull;
    gridbar(gen0, bl);

    const size_t HSEQ = (size_t)BATCH * SEQ * HID;

    for (int chunk = 0; chunk < NCHUNK; ++chunk) {
        // ======== phase A: xg for this chunk ========
        // 2048 jobs: mt (0..63) x nt (0..31, 128-col tiles)
        for (int ti = blk; ti < 2048; ti += NBLK) {
            const int mt = ti >> 5;
            const int nt = ti & 31;
            const int t = chunk * CHUNK + mt;
            const int gcolA = nt * 128 + cloc;
            ull acc[4][4];
#pragma unroll
            for (int i = 0; i < 4; ++i)
#pragma unroll
                for (int c = 0; c < 4; ++c) acc[i][c] = 0ull;

            for (int kc2 = 0; kc2 < 4; ++kc2) {
                const int k0 = kc2 * 128;
                // stage A: 64 rows (b) x 128 k, packed pairs shH[k][pair]
                {
                    int r = tid >> 2, seg = tid & 3;
                    int s = __ldg(src + r * SEQ + t);
                    float* shf = (float*)shH;
#pragma unroll
                    for (int q = 0; q < 8; ++q) {
                        int kk = seg * 32 + q * 4;
                        float4 v = make_float4(0.f, 0.f, 0.f, 0.f);
                        if (s != 0) v = *(const float4*)(emb + (size_t)s * EMB + k0 + kk);
                        shf[(kk + 0) * 64 + r] = v.x;
                        shf[(kk + 1) * 64 + r] = v.y;
                        shf[(kk + 2) * 64 + r] = v.z;
                        shf[(kk + 3) * 64 + r] = v.w;
                    }
                }
                __syncthreads();
                // mac over 128 k, weights from global with depth-4 ring
                {
                    const float* wp = Wi + (size_t)k0 * G4 + gcolA;
                    float4 wb[4];
#pragma unroll
                    for (int j = 0; j < 4; ++j) wb[j] = *(const float4*)(wp + (size_t)j * G4);
#pragma unroll 4
                    for (int k = 0; k < 128; ++k) {
                        float4 wv = wb[k & 3];
                        if (k < 124) wb[k & 3] = *(const float4*)(wp + (size_t)(k + 4) * G4);
                        ull w0 = pk2(wv.x, wv.x), w1 = pk2(wv.y, wv.y);
                        ull w2 = pk2(wv.z, wv.z), w3 = pk2(wv.w, wv.w);
                        const ull* hr = shH + k * 32 + bps * 4;
                        ulonglong2 h01 = *(const ulonglong2*)hr;
                        ulonglong2 h23 = *(const ulonglong2*)(hr + 2);
                        acc[0][0] = ffma2(h01.x, w0, acc[0][0]);
                        acc[0][1] = ffma2(h01.x, w1, acc[0][1]);
                        acc[0][2] = ffma2(h01.x, w2, acc[0][2]);
                        acc[0][3] = ffma2(h01.x, w3, acc[0][3]);
                        acc[1][0] = ffma2(h01.y, w0, acc[1][0]);
                        acc[1][1] = ffma2(h01.y, w1, acc[1][1]);
                        acc[1][2] = ffma2(h01.y, w2, acc[1][2]);
                        acc[1][3] = ffma2(h01.y, w3, acc[1][3]);
                        acc[2][0] = ffma2(h23.x, w0, acc[2][0]);
                        acc[2][1] = ffma2(h23.x, w1, acc[2][1]);
                        acc[2][2] = ffma2(h23.x, w2, acc[2][2]);
                        acc[2][3] = ffma2(h23.x, w3, acc[2][3]);
                        acc[3][0] = ffma2(h23.y, w0, acc[3][0]);
                        acc[3][1] = ffma2(h23.y, w1, acc[3][1]);
                        acc[3][2] = ffma2(h23.y, w2, acc[3][2]);
                        acc[3][3] = ffma2(h23.y, w3, acc[3][3]);
                    }
                }
                __syncthreads();
            }
            float4 bv = *(const float4*)(bi + gcolA);
#pragma unroll
            for (int i = 0; i < 4; ++i) {
                int b0 = (bps * 4 + i) * 2;
                float4 lo4, hi4;
                upk2(acc[i][0], lo4.x, hi4.x); upk2(acc[i][1], lo4.y, hi4.y);
                upk2(acc[i][2], lo4.z, hi4.z); upk2(acc[i][3], lo4.w, hi4.w);
                lo4.x += bv.x; lo4.y += bv.y; lo4.z += bv.z; lo4.w += bv.w;
                hi4.x += bv.x; hi4.y += bv.y; hi4.z += bv.z; hi4.w += bv.w;
                *(float4*)(g_xg + (size_t)(mt * 64 + b0) * G4 + gcolA) = lo4;
                *(float4*)(g_xg + (size_t)(mt * 64 + b0 + 1) * G4 + gcolA) = hi4;
            }
        }
        gridbar(gen0, bl);

        // ======== recurrence over this chunk ========
        for (int tl = 0; tl < CHUNK; ++tl) {
            const int t = chunk * CHUNK + tl;

            // ---- G: partial gate GEMM; weights from persistent smem ----
            {
                // stage h slice: 128 k x 32 pairs, coalesced (k-major global)
                const uint4* hsrc = (const uint4*)(g_hT + (size_t)kbase * 32);
                uint4* hdst = (uint4*)shH;
#pragma unroll
                for (int rr = 0; rr < 8; ++rr) hdst[tid + rr * 256] = __ldcg(hsrc + tid + rr * 256);
                __syncthreads();

                ull acc[4][4];
#pragma unroll
                for (int i = 0; i < 4; ++i)
#pragma unroll
                    for (int c = 0; c < 4; ++c) acc[i][c] = 0ull;

#pragma unroll 8
                for (int k = 0; k < 128; ++k) {
                    float4 wv = *(const float4*)&sW[k * 128 + cloc];
                    ull w0 = pk2(wv.x, wv.x), w1 = pk2(wv.y, wv.y);
                    ull w2 = pk2(wv.z, wv.z), w3 = pk2(wv.w, wv.w);
                    const ull* hr = shH + k * 32 + bps * 4;
                    ulonglong2 h01 = *(const ulonglong2*)hr;
                    ulonglong2 h23 = *(const ulonglong2*)(hr + 2);
                    acc[0][0] = ffma2(h01.x, w0, acc[0][0]);
                    acc[0][1] = ffma2(h01.x, w1, acc[0][1]);
                    acc[0][2] = ffma2(h01.x, w2, acc[0][2]);
                    acc[0][3] = ffma2(h01.x, w3, acc[0][3]);
                    acc[1][0] = ffma2(h01.y, w0, acc[1][0]);
                    acc[1][1] = ffma2(h01.y, w1, acc[1][1]);
                    acc[1][2] = ffma2(h01.y, w2, acc[1][2]);
                    acc[1][3] = ffma2(h01.y, w3, acc[1][3]);
                    acc[2][0] = ffma2(h23.x, w0, acc[2][0]);
                    acc[2][1] = ffma2(h23.x, w1, acc[2][1]);
                    acc[2][2] = ffma2(h23.x, w2, acc[2][2]);
                    acc[2][3] = ffma2(h23.x, w3, acc[2][3]);
                    acc[3][0] = ffma2(h23.y, w0, acc[3][0]);
                    acc[3][1] = ffma2(h23.y, w1, acc[3][1]);
                    acc[3][2] = ffma2(h23.y, w2, acc[3][2]);
                    acc[3][3] = ffma2(h23.y, w3, acc[3][3]);
                }

                const int gcol = cb * 128 + cloc;
#pragma unroll
                for (int i = 0; i < 4; ++i) {
                    int b0 = (bps * 4 + i) * 2;
                    float4 lo4, hi4;
                    upk2(acc[i][0], lo4.x, hi4.x); upk2(acc[i][1], lo4.y, hi4.y);
                    upk2(acc[i][2], lo4.z, hi4.z); upk2(acc[i][3], lo4.w, hi4.w);
                    *(float4*)(g_part + (size_t)(ks * 64 + b0) * G4 + gcol) = lo4;
                    *(float4*)(g_part + (size_t)(ks * 64 + b0 + 1) * G4 + gcol) = hi4;
                }
            }
            gridbar(gen0, bl);

            // ---- R: reduce + gates + c + LN + h (blocks 0..63, one b each) ----
            if (blk < BATCH) {
                const int b = blk;
                float c4[4], o4[4];
                float sum = 0.f;
#pragma unroll
                for (int r = 0; r < 4; ++r) {
                    int j = tid + r * 256;
                    float pg[4];
#pragma unroll
                    for (int gi = 0; gi < 4; ++gi) {
                        int col = gi * HID + j;
                        float s = __ldg(bh + col) +
                                  __ldcg(g_xg + (size_t)(tl * 64 + b) * G4 + col);
#pragma unroll
                        for (int ksi = 0; ksi < 8; ++ksi)
                            s += __ldcg(g_part + (size_t)(ksi * 64 + b) * G4 + col);
                        pg[gi] = s;
                    }
                    float ig = 1.f / (1.f + expf(-pg[0]));
                    float fg = 1.f / (1.f + expf(-pg[1]));
                    float og = 1.f / (1.f + expf(-pg[2]));
                    float gg = tanhf(pg[3]);
                    float cp = g_c[b * HID + j];
                    c4[r] = fg * cp + ig * gg;
                    o4[r] = og;
                    sum += c4[r];
                }
#pragma unroll
                for (int o = 16; o; o >>= 1) sum += __shfl_xor_sync(0xffffffffu, sum, o);
                if ((tid & 31) == 0) rbuf[tid >> 5] = sum;
                __syncthreads();
                if (tid < 8) {
                    float v = rbuf[tid];
#pragma unroll
                    for (int o = 4; o; o >>= 1) v += __shfl_xor_sync(0xffu, v, o);
                    if (tid == 0) s_mu = v * (1.f / 1024.f);
                }
                __syncthreads();
                const float mu = s_mu;
                float vs = 0.f;
#pragma unroll
                for (int r = 0; r < 4; ++r) { float d = c4[r] - mu; vs += d * d; }
#pragma unroll
                for (int o = 16; o; o >>= 1) vs += __shfl_xor_sync(0xffffffffu, vs, o);
                if ((tid & 31) == 0) vbuf[tid >> 5] = vs;
                __syncthreads();
                if (tid < 8) {
                    float v = vbuf[tid];
#pragma unroll
                    for (int o = 4; o; o >>= 1) v += __shfl_xor_sync(0xffu, v, o);
                    if (tid == 0) s_rstd = rsqrtf(v * (1.f / 1024.f) + LNEPS);
                }
                __syncthreads();
                const float rstd = s_rstd;
#pragma unroll
                for (int r = 0; r < 4; ++r) {
                    int j = tid + r * 256;
                    float cn = (c4[r] - mu) * rstd * __ldg(gamma + j) + __ldg(beta + j);
                    g_c[b * HID + j] = cn;
                    float hv = o4[r] * tanhf(cn);
                    ((float*)g_hT)[((size_t)j * 32 + (b >> 1)) * 2 + (b & 1)] = hv;
                    out[((size_t)b * SEQ + t) * HID + j] = hv;
                    if (t == SEQ - 1) {
                        out[HSEQ + (size_t)b * HID + j] = hv;
                        out[HSEQ + (size_t)BATCH * HID + (size_t)b * HID + j] = cn;
                    }
                }
            }
            gridbar(gen0, bl);
        }
    }
}

// ---------------- launch: ONE graph node ----------------
extern "C" void kernel_launch(void* const* d_in, const int* in_sizes, int n_in,
                              void* d_out, int out_size)
{
    const int*   src   = (const int*)  d_in[0];
    const float* emb   = (const float*)d_in[1];
    const float* Wi    = (const float*)d_in[2];
    const float* bi    = (const float*)d_in[3];
    const float* Wh    = (const float*)d_in[4];
    const float* bh    = (const float*)d_in[5];
    const float* gamma = (const float*)d_in[6];
    const float* beta  = (const float*)d_in[7];
    float* out = (float*)d_out;

    const int dsmem = 65536 + 32768;   // sW 64KB + shH 32KB
    cudaFuncSetAttribute(encPersist, cudaFuncAttributeMaxDynamicSharedMemorySize, dsmem);
    encPersist<<<NBLK, 256, dsmem>>>(src, emb, Wi, bi, Wh, bh, gamma, beta, out);
}